// round 11
// baseline (speedup 1.0000x reference)
#include <cuda_runtime.h>
#include <math.h>

// Problem sizes (fixed by the reference)
#define BB 256
#define DD 512
#define HH 512

// Scratch: projections q,k,v,i,f,o  -> 6 * 256 * 512 * 4B = 3 MB
__device__ float g_proj[6][BB][HH];

struct GemmArgs {
    const float* x;        // [B, D] row-major
    const float* W[6];     // each [H, D] row-major (x @ W.T => dot of rows)
    const float* bias[3];  // b_i, b_f, b_o (for which = 3,4,5)
};

// Fused 6-way projection GEMM: M=256, N=3072 (6*512), K=512.
// 32x64 tiles, 384 blocks x 128 threads (fine-grained balance, ~2.6 blocks/SM),
// 4x4 microtile (8x16 thread grid), BK=16 double-buffered smem,
// one __syncthreads per k-tile, register prefetch of next gmem tile.
__global__ __launch_bounds__(128) void proj_kernel(GemmArgs a) {
    const int BK = 16;
    __shared__ float As[2][BK][32];   // As[buf][k][m]
    __shared__ float Bs[2][BK][64];   // Bs[buf][k][n]

    const int n_tile = blockIdx.x;           // 0..47
    const int m_tile = blockIdx.y;           // 0..7
    const int which  = (n_tile * 64) / HH;   // which weight matrix
    const int h0     = (n_tile * 64) % HH;   // column offset within that matrix
    const int row0   = m_tile * 32;

    const float* __restrict__ W = a.W[which];
    const float* __restrict__ x = a.x;

    const int tid = threadIdx.x;
    // A loader: 128 float4s (32 rows x 4 along K) -> 1 per thread
    const int arow = tid >> 2;           // 0..31
    const int akq  = (tid & 3) * 4;      // 0,4,8,12
    // B loader: 256 float4s (64 rows x 4 along K) -> 2 per thread
    const int brow0 = tid >> 2;          // 0..31
    const int bkq   = (tid & 3) * 4;     // 0,4,8,12
    const int brow1 = brow0 + 32;        // 32..63
    // Compute mapping: 8x16 thread grid of 4x4 micro-tiles
    const int tr = tid >> 4;             // 0..7  -> rows tr*4..+3
    const int tc = tid & 15;             // 0..15 -> cols tc*4..+3

    float acc[4][4];
#pragma unroll
    for (int i = 0; i < 4; i++)
#pragma unroll
        for (int j = 0; j < 4; j++) acc[i][j] = 0.0f;

    const float* gA  = x + (size_t)(row0 + arow) * DD + akq;
    const float* gB0 = W + (size_t)(h0 + brow0) * DD + bkq;
    const float* gB1 = W + (size_t)(h0 + brow1) * DD + bkq;

    // Prologue: k-tile 0 -> smem buf 0
    float4 ra  = *(const float4*)gA;
    float4 rb0 = *(const float4*)gB0;
    float4 rb1 = *(const float4*)gB1;
    As[0][akq + 0][arow] = ra.x;  As[0][akq + 1][arow] = ra.y;
    As[0][akq + 2][arow] = ra.z;  As[0][akq + 3][arow] = ra.w;
    Bs[0][bkq + 0][brow0] = rb0.x; Bs[0][bkq + 1][brow0] = rb0.y;
    Bs[0][bkq + 2][brow0] = rb0.z; Bs[0][bkq + 3][brow0] = rb0.w;
    Bs[0][bkq + 0][brow1] = rb1.x; Bs[0][bkq + 1][brow1] = rb1.y;
    Bs[0][bkq + 2][brow1] = rb1.z; Bs[0][bkq + 3][brow1] = rb1.w;
    __syncthreads();

    const int T = DD / BK;  // 32 k-tiles
#pragma unroll 1
    for (int t = 0; t < T; t++) {
        const int cur = t & 1;
        const int nxt = cur ^ 1;

        // Prefetch next k-tile into registers (latency hidden under compute)
        if (t + 1 < T) {
            ra  = *(const float4*)(gA  + (t + 1) * BK);
            rb0 = *(const float4*)(gB0 + (t + 1) * BK);
            rb1 = *(const float4*)(gB1 + (t + 1) * BK);
        }

        // 16 kk steps x (2 LDS.128 + 16 FFMA)  -> 0.5 smem floats per FMA
#pragma unroll
        for (int kk = 0; kk < BK; kk++) {
            const float4 av = *(const float4*)&As[cur][kk][tr * 4];
            const float4 bv = *(const float4*)&Bs[cur][kk][tc * 4];
            const float ar[4] = {av.x, av.y, av.z, av.w};
            const float br[4] = {bv.x, bv.y, bv.z, bv.w};
#pragma unroll
            for (int i = 0; i < 4; i++)
#pragma unroll
                for (int j = 0; j < 4; j++) acc[i][j] = fmaf(ar[i], br[j], acc[i][j]);
        }

        if (t + 1 < T) {
            As[nxt][akq + 0][arow] = ra.x;  As[nxt][akq + 1][arow] = ra.y;
            As[nxt][akq + 2][arow] = ra.z;  As[nxt][akq + 3][arow] = ra.w;
            Bs[nxt][bkq + 0][brow0] = rb0.x; Bs[nxt][bkq + 1][brow0] = rb0.y;
            Bs[nxt][bkq + 2][brow0] = rb0.z; Bs[nxt][bkq + 3][brow0] = rb0.w;
            Bs[nxt][bkq + 0][brow1] = rb1.x; Bs[nxt][bkq + 1][brow1] = rb1.y;
            Bs[nxt][bkq + 2][brow1] = rb1.z; Bs[nxt][bkq + 3][brow1] = rb1.w;
        }
        __syncthreads();
    }

    // Epilogue: bias + sigmoid for i/f/o, write to scratch
    const bool gate = (which >= 3);
    const float* __restrict__ bias = gate ? a.bias[which - 3] : nullptr;
#pragma unroll
    for (int i = 0; i < 4; i++) {
        const int r = row0 + tr * 4 + i;
#pragma unroll
        for (int j = 0; j < 4; j++) {
            const int h = h0 + tc * 4 + j;
            float v = acc[i][j];
            if (gate) {
                v += bias[h];
                v = 1.0f / (1.0f + __expf(-v));
            }
            g_proj[which][r][h] = v;
        }
    }
}

// Fused state update + readout — R1 form, measured 78.6-79.6us @ ~78% DRAM.
// DO NOT MODIFY: interleaved load->fma->store (MLP_p1 ~1) is deliberate;
// front-batched LDGs and .cs hints both measurably regress this kernel.
// One warp per (b, i) row; block = 16 warps; grid (H/16, B).
__global__ __launch_bounds__(512) void update_kernel(const float* __restrict__ Cprev,
                                                     float* __restrict__ out_h,
                                                     float* __restrict__ out_C) {
    __shared__ float sv[HH];
    __shared__ float sq[HH];

    const int b   = blockIdx.y;
    const int i0  = blockIdx.x * 16;
    const int tid = threadIdx.x;

    // Stage v[b,:] and q[b,:] (shared across all 16 rows of this block)
    sv[tid] = g_proj[2][b][tid];
    sq[tid] = g_proj[0][b][tid];
    __syncthreads();

    const int warp = tid >> 5;
    const int lane = tid & 31;
    const int i    = i0 + warp;

    const float f_bi = g_proj[4][b][i];
    const float ik   = g_proj[3][b][i] * g_proj[1][b][i];
    const float o_bi = g_proj[5][b][i];

    const size_t rowoff = ((size_t)b * HH + i) * HH;
    const float4* __restrict__ Cp = (const float4*)(Cprev + rowoff);
    float4* __restrict__ Ct       = (float4*)(out_C + rowoff);
    const float4* __restrict__ v4 = (const float4*)sv;
    const float4* __restrict__ q4 = (const float4*)sq;

    float acc = 0.0f;
#pragma unroll
    for (int it = 0; it < 4; it++) {
        const int j4 = it * 32 + lane;    // 128 float4s per row
        float4 c = Cp[j4];
        const float4 vv = v4[j4];
        const float4 qq = q4[j4];
        c.x = fmaf(f_bi, c.x, ik * vv.x);
        c.y = fmaf(f_bi, c.y, ik * vv.y);
        c.z = fmaf(f_bi, c.z, ik * vv.z);
        c.w = fmaf(f_bi, c.w, ik * vv.w);
        Ct[j4] = c;
        acc += c.x * qq.x + c.y * qq.y + c.z * qq.z + c.w * qq.w;
    }

    // Warp reduction for the dot product
#pragma unroll
    for (int off = 16; off > 0; off >>= 1)
        acc += __shfl_xor_sync(0xFFFFFFFFu, acc, off);

    if (lane == 0) out_h[(size_t)b * HH + i] = o_bi * tanhf(acc);
}

extern "C" void kernel_launch(void* const* d_in, const int* in_sizes, int n_in,
                              void* d_out, int out_size) {
    // Inputs: 0:x 1:h_prev(unused) 2:C_prev 3:W_q 4:W_k 5:W_v 6:W_i 7:W_f 8:W_o 9:b_i 10:b_f 11:b_o
    const float* x     = (const float*)d_in[0];
    const float* Cprev = (const float*)d_in[2];

    GemmArgs a;
    a.x = x;
    a.W[0] = (const float*)d_in[3];
    a.W[1] = (const float*)d_in[4];
    a.W[2] = (const float*)d_in[5];
    a.W[3] = (const float*)d_in[6];
    a.W[4] = (const float*)d_in[7];
    a.W[5] = (const float*)d_in[8];
    a.bias[0] = (const float*)d_in[9];
    a.bias[1] = (const float*)d_in[10];
    a.bias[2] = (const float*)d_in[11];

    float* out = (float*)d_out;
    float* out_h = out;                       // [B, H]
    float* out_C = out + (size_t)BB * HH;     // [B, H, H]

    dim3 gGemm(48, 8);            // 384 blocks: 32x64 tiles, fine-grained balance
    proj_kernel<<<gGemm, 128>>>(a);

    dim3 gUpd(HH / 16, BB);       // (32, 256) blocks, 512 threads
    update_kernel<<<gUpd, 512>>>(Cprev, out_h, out_C);
}

// round 12
// speedup vs baseline: 1.2890x; 1.2890x over previous
#include <cuda_runtime.h>
#include <math.h>

// Problem sizes (fixed by the reference)
#define BB 256
#define DD 512
#define HH 512

// Scratch: split-K partial sums (2 halves) + final projections
__device__ float g_part[2][6][BB][HH];   // 6 MB
__device__ float g_proj[6][BB][HH];      // 3 MB

struct GemmArgs {
    const float* x;        // [B, D] row-major
    const float* W[6];     // each [H, D] row-major (x @ W.T => dot of rows)
    const float* bias[3];  // b_i, b_f, b_o (for which = 3,4,5)
};

// Fused 6-way projection GEMM with split-K: M=256, N=3072 (6*512), K=512.
// Proven R5 block design: 64x64 tile, 256 threads, 4x4 microtile, BK=16
// double-buffered, one __syncthreads per k-tile, register prefetch.
// blockIdx.z in {0,1} selects the K half -> 384 blocks of ~11us each,
// which packs 148 SMs evenly (296 wave-1 + 88 wave-2) instead of the
// 2x-straggler imbalance of 192 big blocks.
__global__ __launch_bounds__(256) void proj_kernel(GemmArgs a) {
    const int BK = 16;
    __shared__ float As[2][BK][64];   // As[buf][k][m]
    __shared__ float Bs[2][BK][64];   // Bs[buf][k][n]

    const int n_tile = blockIdx.x;           // 0..47
    const int m_tile = blockIdx.y;           // 0..3
    const int kz     = blockIdx.z;           // 0..1 (K half)
    const int which  = (n_tile * 64) / HH;   // which weight matrix
    const int h0     = (n_tile * 64) % HH;   // column offset within that matrix
    const int row0   = m_tile * 64;
    const int k0base = kz * (DD / 2);        // 0 or 256

    const float* __restrict__ W = a.W[which];
    const float* __restrict__ x = a.x;

    const int tid  = threadIdx.x;
    // Loader mapping: 4 threads per row, each one float4 along K
    const int lrow = tid >> 2;         // 0..63
    const int lk   = (tid & 3) * 4;    // 0,4,8,12
    // Compute mapping: 16x16 thread grid of 4x4 micro-tiles
    const int tr = tid >> 4;           // 0..15 -> rows tr*4..+3
    const int tc = tid & 15;           // 0..15 -> cols tc*4..+3

    float acc[4][4];
#pragma unroll
    for (int i = 0; i < 4; i++)
#pragma unroll
        for (int j = 0; j < 4; j++) acc[i][j] = 0.0f;

    const float* gA = x + (size_t)(row0 + lrow) * DD + k0base + lk;
    const float* gB = W + (size_t)(h0 + lrow) * DD + k0base + lk;

    // Prologue: k-tile 0 -> smem buf 0
    float4 ra = *(const float4*)gA;
    float4 rb = *(const float4*)gB;
    As[0][lk + 0][lrow] = ra.x; As[0][lk + 1][lrow] = ra.y;
    As[0][lk + 2][lrow] = ra.z; As[0][lk + 3][lrow] = ra.w;
    Bs[0][lk + 0][lrow] = rb.x; Bs[0][lk + 1][lrow] = rb.y;
    Bs[0][lk + 2][lrow] = rb.z; Bs[0][lk + 3][lrow] = rb.w;
    __syncthreads();

    const int T = (DD / 2) / BK;  // 16 k-tiles per half
#pragma unroll 1
    for (int t = 0; t < T; t++) {
        const int cur = t & 1;
        const int nxt = cur ^ 1;

        // Prefetch next k-tile into registers (latency under compute)
        if (t + 1 < T) {
            ra = *(const float4*)(gA + (t + 1) * BK);
            rb = *(const float4*)(gB + (t + 1) * BK);
        }

        // 16 kk steps x (2 LDS.128 + 16 FFMA) -> 0.5 smem floats per FMA
#pragma unroll
        for (int kk = 0; kk < BK; kk++) {
            const float4 av = *(const float4*)&As[cur][kk][tr * 4];
            const float4 bv = *(const float4*)&Bs[cur][kk][tc * 4];
            const float ar[4] = {av.x, av.y, av.z, av.w};
            const float br[4] = {bv.x, bv.y, bv.z, bv.w};
#pragma unroll
            for (int i = 0; i < 4; i++)
#pragma unroll
                for (int j = 0; j < 4; j++) acc[i][j] = fmaf(ar[i], br[j], acc[i][j]);
        }

        if (t + 1 < T) {
            As[nxt][lk + 0][lrow] = ra.x; As[nxt][lk + 1][lrow] = ra.y;
            As[nxt][lk + 2][lrow] = ra.z; As[nxt][lk + 3][lrow] = ra.w;
            Bs[nxt][lk + 0][lrow] = rb.x; Bs[nxt][lk + 1][lrow] = rb.y;
            Bs[nxt][lk + 2][lrow] = rb.z; Bs[nxt][lk + 3][lrow] = rb.w;
        }
        __syncthreads();
    }

    // Write raw partial sums (bias/sigmoid applied in reduce pass)
#pragma unroll
    for (int i = 0; i < 4; i++) {
        const int r = row0 + tr * 4 + i;
#pragma unroll
        for (int j = 0; j < 4; j++) {
            g_part[kz][which][r][h0 + tc * 4 + j] = acc[i][j];
        }
    }
}

// Reduce pass: sum the two K halves, apply bias + sigmoid for i/f/o.
// 196608 float4s total; vectorized, ~9 MB traffic (~2-3us).
__global__ __launch_bounds__(256) void reduce_kernel(const float* __restrict__ b_i,
                                                     const float* __restrict__ b_f,
                                                     const float* __restrict__ b_o) {
    const int f4 = blockIdx.x * 256 + threadIdx.x;      // 0..196607
    const int per_mat = BB * HH / 4;                    // 32768 float4 per matrix
    const int which = f4 / per_mat;
    const int rem   = f4 - which * per_mat;
    const int h4    = (rem & (HH / 4 - 1)) * 4;         // column of first elem

    const float4* p0 = (const float4*)&g_part[0][0][0][0];
    const float4* p1 = (const float4*)&g_part[1][0][0][0];
    float4 s0 = p0[f4];
    float4 s1 = p1[f4];
    float4 s;
    s.x = s0.x + s1.x;  s.y = s0.y + s1.y;
    s.z = s0.z + s1.z;  s.w = s0.w + s1.w;

    if (which >= 3) {
        const float* bias = (which == 3) ? b_i : (which == 4) ? b_f : b_o;
        s.x = 1.0f / (1.0f + __expf(-(s.x + bias[h4 + 0])));
        s.y = 1.0f / (1.0f + __expf(-(s.y + bias[h4 + 1])));
        s.z = 1.0f / (1.0f + __expf(-(s.z + bias[h4 + 2])));
        s.w = 1.0f / (1.0f + __expf(-(s.w + bias[h4 + 3])));
    }
    ((float4*)&g_proj[0][0][0])[f4] = s;
}

// Fused state update + readout — R1 form, measured 78.6-79.6us @ ~78% DRAM.
// DO NOT MODIFY: interleaved load->fma->store (MLP_p1 ~1) is deliberate;
// front-batched LDGs and .cs hints both measurably regress this kernel.
// One warp per (b, i) row; block = 16 warps; grid (H/16, B).
__global__ __launch_bounds__(512) void update_kernel(const float* __restrict__ Cprev,
                                                     float* __restrict__ out_h,
                                                     float* __restrict__ out_C) {
    __shared__ float sv[HH];
    __shared__ float sq[HH];

    const int b   = blockIdx.y;
    const int i0  = blockIdx.x * 16;
    const int tid = threadIdx.x;

    // Stage v[b,:] and q[b,:] (shared across all 16 rows of this block)
    sv[tid] = g_proj[2][b][tid];
    sq[tid] = g_proj[0][b][tid];
    __syncthreads();

    const int warp = tid >> 5;
    const int lane = tid & 31;
    const int i    = i0 + warp;

    const float f_bi = g_proj[4][b][i];
    const float ik   = g_proj[3][b][i] * g_proj[1][b][i];
    const float o_bi = g_proj[5][b][i];

    const size_t rowoff = ((size_t)b * HH + i) * HH;
    const float4* __restrict__ Cp = (const float4*)(Cprev + rowoff);
    float4* __restrict__ Ct       = (float4*)(out_C + rowoff);
    const float4* __restrict__ v4 = (const float4*)sv;
    const float4* __restrict__ q4 = (const float4*)sq;

    float acc = 0.0f;
#pragma unroll
    for (int it = 0; it < 4; it++) {
        const int j4 = it * 32 + lane;    // 128 float4s per row
        float4 c = Cp[j4];
        const float4 vv = v4[j4];
        const float4 qq = q4[j4];
        c.x = fmaf(f_bi, c.x, ik * vv.x);
        c.y = fmaf(f_bi, c.y, ik * vv.y);
        c.z = fmaf(f_bi, c.z, ik * vv.z);
        c.w = fmaf(f_bi, c.w, ik * vv.w);
        Ct[j4] = c;
        acc += c.x * qq.x + c.y * qq.y + c.z * qq.z + c.w * qq.w;
    }

    // Warp reduction for the dot product
#pragma unroll
    for (int off = 16; off > 0; off >>= 1)
        acc += __shfl_xor_sync(0xFFFFFFFFu, acc, off);

    if (lane == 0) out_h[(size_t)b * HH + i] = o_bi * tanhf(acc);
}

extern "C" void kernel_launch(void* const* d_in, const int* in_sizes, int n_in,
                              void* d_out, int out_size) {
    // Inputs: 0:x 1:h_prev(unused) 2:C_prev 3:W_q 4:W_k 5:W_v 6:W_i 7:W_f 8:W_o 9:b_i 10:b_f 11:b_o
    const float* x     = (const float*)d_in[0];
    const float* Cprev = (const float*)d_in[2];

    GemmArgs a;
    a.x = x;
    a.W[0] = (const float*)d_in[3];
    a.W[1] = (const float*)d_in[4];
    a.W[2] = (const float*)d_in[5];
    a.W[3] = (const float*)d_in[6];
    a.W[4] = (const float*)d_in[7];
    a.W[5] = (const float*)d_in[8];
    a.bias[0] = (const float*)d_in[9];
    a.bias[1] = (const float*)d_in[10];
    a.bias[2] = (const float*)d_in[11];

    float* out = (float*)d_out;
    float* out_h = out;                       // [B, H]
    float* out_C = out + (size_t)BB * HH;     // [B, H, H]

    dim3 gGemm(48, 4, 2);         // 384 blocks: 64x64 tiles x 2 K-halves
    proj_kernel<<<gGemm, 256>>>(a);

    reduce_kernel<<<196608 / 256, 256>>>((const float*)d_in[9],
                                         (const float*)d_in[10],
                                         (const float*)d_in[11]);

    dim3 gUpd(HH / 16, BB);       // (32, 256) blocks, 512 threads
    update_kernel<<<gUpd, 512>>>(Cprev, out_h, out_C);
}

// round 16
// speedup vs baseline: 1.3567x; 1.0525x over previous
#include <cuda_runtime.h>
#include <math.h>

// Problem sizes (fixed by the reference)
#define BB 256
#define DD 512
#define HH 512

#define KSPLIT 4

// Scratch: split-K partial sums + final projections
__device__ float g_part[KSPLIT][6][BB][HH];   // 12 MB
__device__ float g_proj[6][BB][HH];           // 3 MB

struct GemmArgs {
    const float* x;        // [B, D] row-major
    const float* W[6];     // each [H, D] row-major (x @ W.T => dot of rows)
};

// ---- packed f32x2 helpers (sm_103a FFMA2; only reachable via PTX) ----
__device__ __forceinline__ unsigned long long bcast2(float a) {
    unsigned long long r;
    asm("mov.b64 %0, {%1, %1};" : "=l"(r) : "f"(a));
    return r;
}
__device__ __forceinline__ unsigned long long fma2(unsigned long long a,
                                                   unsigned long long b,
                                                   unsigned long long c) {
    unsigned long long d;
    asm("fma.rn.f32x2 %0, %1, %2, %3;" : "=l"(d) : "l"(a), "l"(b), "l"(c));
    return d;
}

// Fused 6-way projection GEMM, split-K 4: M=256, N=3072 (6*512), K=512.
// 64x128 tile, 256 threads, 4x8 microtile with packed FFMA2 (32 products per
// 19 issue slots), BK=16 double-buffered smem, one __syncthreads per k-tile.
// 24 n-tiles x 4 m-tiles x 4 K-quarters = 384 blocks (proven-balanced count;
// per-block FMA work identical to the R12 winner, at ~2x pipe efficiency).
// Each 128-wide N tile lies entirely within one weight matrix (128 | 512).
__global__ __launch_bounds__(256) void proj_kernel(GemmArgs a) {
    const int BK = 16;
    __shared__ float As[2][BK][64];    // As[buf][k][m]
    __shared__ float Bs[2][BK][128];   // Bs[buf][k][n]

    const int n_tile = blockIdx.x;            // 0..23
    const int m_tile = blockIdx.y;            // 0..3
    const int kz     = blockIdx.z;            // 0..3 (K quarter)
    const int which  = (n_tile * 128) / HH;   // which weight matrix
    const int h0     = (n_tile * 128) % HH;   // column offset within matrix
    const int row0   = m_tile * 64;
    const int k0base = kz * (DD / KSPLIT);    // 0,128,256,384

    const float* __restrict__ W = a.W[which];
    const float* __restrict__ x = a.x;

    const int tid = threadIdx.x;
    // A loader: 256 float4s (64 rows x 4 along K) -> 1 per thread
    const int arow = tid >> 2;          // 0..63
    const int akq  = (tid & 3) * 4;     // 0,4,8,12
    // B loader: 512 float4s (128 rows x 4) -> 2 per thread
    const int brow0 = tid >> 2;         // 0..63
    const int bkq   = (tid & 3) * 4;
    const int brow1 = brow0 + 64;       // 64..127
    // Compute mapping: 16x16 thread grid; each thread: rows tr*4..+3,
    // cols {tc*4..+3} and {64+tc*4..+3} (split halves keep LDS conflict-free)
    const int tr = tid >> 4;            // 0..15
    const int tc = tid & 15;            // 0..15

    unsigned long long acc2[4][4];      // [row][colpair]: pairs (c,c+1)
#pragma unroll
    for (int i = 0; i < 4; i++)
#pragma unroll
        for (int j = 0; j < 4; j++) acc2[i][j] = 0ull;

    const float* gA  = x + (size_t)(row0 + arow) * DD + k0base + akq;
    const float* gB0 = W + (size_t)(h0 + brow0) * DD + k0base + bkq;
    const float* gB1 = W + (size_t)(h0 + brow1) * DD + k0base + bkq;

    // Prologue: k-tile 0 -> smem buf 0
    float4 ra  = *(const float4*)gA;
    float4 rb0 = *(const float4*)gB0;
    float4 rb1 = *(const float4*)gB1;
    As[0][akq + 0][arow] = ra.x;  As[0][akq + 1][arow] = ra.y;
    As[0][akq + 2][arow] = ra.z;  As[0][akq + 3][arow] = ra.w;
    Bs[0][bkq + 0][brow0] = rb0.x; Bs[0][bkq + 1][brow0] = rb0.y;
    Bs[0][bkq + 2][brow0] = rb0.z; Bs[0][bkq + 3][brow0] = rb0.w;
    Bs[0][bkq + 0][brow1] = rb1.x; Bs[0][bkq + 1][brow1] = rb1.y;
    Bs[0][bkq + 2][brow1] = rb1.z; Bs[0][bkq + 3][brow1] = rb1.w;
    __syncthreads();

    const int T = (DD / KSPLIT) / BK;  // 8 k-tiles per quarter
#pragma unroll 1
    for (int t = 0; t < T; t++) {
        const int cur = t & 1;
        const int nxt = cur ^ 1;

        // Prefetch next k-tile into registers (latency under compute)
        if (t + 1 < T) {
            ra  = *(const float4*)(gA  + (t + 1) * BK);
            rb0 = *(const float4*)(gB0 + (t + 1) * BK);
            rb1 = *(const float4*)(gB1 + (t + 1) * BK);
        }

        // 16 kk steps x (3 LDS.128 + 4 MOV64 + 16 FFMA2) -> 32 products/step
#pragma unroll
        for (int kk = 0; kk < BK; kk++) {
            const float4 av  = *(const float4*)&As[cur][kk][tr * 4];
            const float4 bv0 = *(const float4*)&Bs[cur][kk][tc * 4];        // cols tc*4..+3
            const float4 bv1 = *(const float4*)&Bs[cur][kk][64 + tc * 4];   // cols 64+tc*4..+3

            unsigned long long ap[4];
            ap[0] = bcast2(av.x); ap[1] = bcast2(av.y);
            ap[2] = bcast2(av.z); ap[3] = bcast2(av.w);

            unsigned long long bp[4];
            bp[0] = ((const unsigned long long*)&bv0)[0];   // cols tc*4+0,1
            bp[1] = ((const unsigned long long*)&bv0)[1];   // cols tc*4+2,3
            bp[2] = ((const unsigned long long*)&bv1)[0];   // cols 64+tc*4+0,1
            bp[3] = ((const unsigned long long*)&bv1)[1];   // cols 64+tc*4+2,3

#pragma unroll
            for (int i = 0; i < 4; i++)
#pragma unroll
                for (int j = 0; j < 4; j++)
                    acc2[i][j] = fma2(ap[i], bp[j], acc2[i][j]);
        }

        if (t + 1 < T) {
            As[nxt][akq + 0][arow] = ra.x;  As[nxt][akq + 1][arow] = ra.y;
            As[nxt][akq + 2][arow] = ra.z;  As[nxt][akq + 3][arow] = ra.w;
            Bs[nxt][bkq + 0][brow0] = rb0.x; Bs[nxt][bkq + 1][brow0] = rb0.y;
            Bs[nxt][bkq + 2][brow0] = rb0.z; Bs[nxt][bkq + 3][brow0] = rb0.w;
            Bs[nxt][bkq + 0][brow1] = rb1.x; Bs[nxt][bkq + 1][brow1] = rb1.y;
            Bs[nxt][bkq + 2][brow1] = rb1.z; Bs[nxt][bkq + 3][brow1] = rb1.w;
        }
        __syncthreads();
    }

    // Write raw partial sums as float2 pairs (bias/sigmoid in reduce pass)
#pragma unroll
    for (int i = 0; i < 4; i++) {
        const int r = row0 + tr * 4 + i;
        float* rowp = &g_part[kz][which][r][h0];
#pragma unroll
        for (int j = 0; j < 2; j++)
            *(float2*)&rowp[tc * 4 + j * 2]      = *(float2*)&acc2[i][j];
#pragma unroll
        for (int j = 2; j < 4; j++)
            *(float2*)&rowp[64 + tc * 4 + (j - 2) * 2] = *(float2*)&acc2[i][j];
    }
}

// Reduce pass: sum the 4 K quarters, apply bias + sigmoid for i/f/o.
// 12 MB reads (L2-resident) + 3 MB write; ~2.5us.
__global__ __launch_bounds__(256) void reduce_kernel(const float* __restrict__ b_i,
                                                     const float* __restrict__ b_f,
                                                     const float* __restrict__ b_o) {
    const int f4 = blockIdx.x * 256 + threadIdx.x;      // 0..196607
    const int per_mat = BB * HH / 4;                    // 32768 float4 per matrix
    const int which = f4 / per_mat;
    const int rem   = f4 - which * per_mat;
    const int h4    = (rem & (HH / 4 - 1)) * 4;         // column of first elem

    const float4* p0 = (const float4*)&g_part[0][0][0][0];
    const float4* p1 = (const float4*)&g_part[1][0][0][0];
    const float4* p2 = (const float4*)&g_part[2][0][0][0];
    const float4* p3 = (const float4*)&g_part[3][0][0][0];
    float4 s0 = p0[f4], s1 = p1[f4], s2 = p2[f4], s3 = p3[f4];
    float4 s;
    s.x = (s0.x + s1.x) + (s2.x + s3.x);
    s.y = (s0.y + s1.y) + (s2.y + s3.y);
    s.z = (s0.z + s1.z) + (s2.z + s3.z);
    s.w = (s0.w + s1.w) + (s2.w + s3.w);

    if (which >= 3) {
        const float* bias = (which == 3) ? b_i : (which == 4) ? b_f : b_o;
        s.x = 1.0f / (1.0f + __expf(-(s.x + bias[h4 + 0])));
        s.y = 1.0f / (1.0f + __expf(-(s.y + bias[h4 + 1])));
        s.z = 1.0f / (1.0f + __expf(-(s.z + bias[h4 + 2])));
        s.w = 1.0f / (1.0f + __expf(-(s.w + bias[h4 + 3])));
    }
    ((float4*)&g_proj[0][0][0])[f4] = s;
}

// Fused state update + readout — R1 form, measured 78.6-79.6us @ ~78% DRAM.
// DO NOT MODIFY: interleaved load->fma->store (MLP_p1 ~1) is deliberate;
// front-batched LDGs and .cs hints both measurably regress this kernel.
// One warp per (b, i) row; block = 16 warps; grid (H/16, B).
__global__ __launch_bounds__(512) void update_kernel(const float* __restrict__ Cprev,
                                                     float* __restrict__ out_h,
                                                     float* __restrict__ out_C) {
    __shared__ float sv[HH];
    __shared__ float sq[HH];

    const int b   = blockIdx.y;
    const int i0  = blockIdx.x * 16;
    const int tid = threadIdx.x;

    // Stage v[b,:] and q[b,:] (shared across all 16 rows of this block)
    sv[tid] = g_proj[2][b][tid];
    sq[tid] = g_proj[0][b][tid];
    __syncthreads();

    const int warp = tid >> 5;
    const int lane = tid & 31;
    const int i    = i0 + warp;

    const float f_bi = g_proj[4][b][i];
    const float ik   = g_proj[3][b][i] * g_proj[1][b][i];
    const float o_bi = g_proj[5][b][i];

    const size_t rowoff = ((size_t)b * HH + i) * HH;
    const float4* __restrict__ Cp = (const float4*)(Cprev + rowoff);
    float4* __restrict__ Ct       = (float4*)(out_C + rowoff);
    const float4* __restrict__ v4 = (const float4*)sv;
    const float4* __restrict__ q4 = (const float4*)sq;

    float acc = 0.0f;
#pragma unroll
    for (int it = 0; it < 4; it++) {
        const int j4 = it * 32 + lane;    // 128 float4s per row
        float4 c = Cp[j4];
        const float4 vv = v4[j4];
        const float4 qq = q4[j4];
        c.x = fmaf(f_bi, c.x, ik * vv.x);
        c.y = fmaf(f_bi, c.y, ik * vv.y);
        c.z = fmaf(f_bi, c.z, ik * vv.z);
        c.w = fmaf(f_bi, c.w, ik * vv.w);
        Ct[j4] = c;
        acc += c.x * qq.x + c.y * qq.y + c.z * qq.z + c.w * qq.w;
    }

    // Warp reduction for the dot product
#pragma unroll
    for (int off = 16; off > 0; off >>= 1)
        acc += __shfl_xor_sync(0xFFFFFFFFu, acc, off);

    if (lane == 0) out_h[(size_t)b * HH + i] = o_bi * tanhf(acc);
}

extern "C" void kernel_launch(void* const* d_in, const int* in_sizes, int n_in,
                              void* d_out, int out_size) {
    // Inputs: 0:x 1:h_prev(unused) 2:C_prev 3:W_q 4:W_k 5:W_v 6:W_i 7:W_f 8:W_o 9:b_i 10:b_f 11:b_o
    const float* x     = (const float*)d_in[0];
    const float* Cprev = (const float*)d_in[2];

    GemmArgs a;
    a.x = x;
    a.W[0] = (const float*)d_in[3];
    a.W[1] = (const float*)d_in[4];
    a.W[2] = (const float*)d_in[5];
    a.W[3] = (const float*)d_in[6];
    a.W[4] = (const float*)d_in[7];
    a.W[5] = (const float*)d_in[8];

    float* out = (float*)d_out;
    float* out_h = out;                       // [B, H]
    float* out_C = out + (size_t)BB * HH;     // [B, H, H]

    dim3 gGemm(24, 4, KSPLIT);    // 384 blocks: 64x128 tiles x 4 K-quarters
    proj_kernel<<<gGemm, 256>>>(a);

    reduce_kernel<<<196608 / 256, 256>>>((const float*)d_in[9],
                                         (const float*)d_in[10],
                                         (const float*)d_in[11]);

    dim3 gUpd(HH / 16, BB);       // (32, 256) blocks, 512 threads
    update_kernel<<<gUpd, 512>>>(Cprev, out_h, out_C);
}